// round 2
// baseline (speedup 1.0000x reference)
#include <cuda_runtime.h>
#include <math_constants.h>
#include <cstddef>

// Problem shape (fixed by reference)
#define BB  4
#define SS  2048
#define EE  1024
#define HH  64
#define NROWS (BB*SS)     // 8192 total query rows
#define CH  128           // keys per split-K chunk
#define NCH (SS/CH)       // 16 chunks per batch

// -------- device scratch (no allocations allowed in kernel_launch) --------
__device__ float g_q[NROWS*HH];
__device__ float g_k[NROWS*HH];
__device__ float g_v[NROWS*HH];
__device__ float g_opart[(size_t)NROWS*NCH*HH];   // unnormalized partial outputs
__device__ float g_ml[(size_t)NROWS*NCH*2];       // per-chunk (m, l)

// ==========================================================================
// Kernel 1: QKV projection, one output matrix per blockIdx.y.
// Block: 256 threads computes 64 rows x 64 cols of one projection.
// Grid (128, 3) = 384 blocks -> ~2.6 waves, ~55 regs -> several CTAs/SM.
// ==========================================================================
__global__ __launch_bounds__(256) void qkv_proj(
    const float* __restrict__ x,
    const float* __restrict__ Wq, const float* __restrict__ bq,
    const float* __restrict__ Wk, const float* __restrict__ bk,
    const float* __restrict__ Wv, const float* __restrict__ bv)
{
    __shared__ float xs[64][17];          // +1 pad (scalar broadcast reads)
    __shared__ float ws[16][64];

    const int tid  = threadIdx.x;
    const int ty   = tid >> 4;            // 0..15 row group
    const int tx   = tid & 15;            // 0..15 col group
    const int row0 = blockIdx.x * 64;
    const int mat  = blockIdx.y;          // 0=Q, 1=K, 2=V

    const float* W    = (mat == 0) ? Wq : (mat == 1) ? Wk : Wv;
    const float* bias = (mat == 0) ? bq : (mat == 1) ? bk : bv;
    float* out        = (mat == 0) ? g_q : (mat == 1) ? g_k : g_v;

    float acc[4][4] = {};

    for (int kb = 0; kb < EE; kb += 16) {
        {   // x tile: 64x16, one float4 per thread
            int idx = tid * 4;
            int rr = idx >> 4;
            int cc = idx & 15;
            float4 t = *(const float4*)&x[(size_t)(row0 + rr) * EE + kb + cc];
            xs[rr][cc+0] = t.x; xs[rr][cc+1] = t.y;
            xs[rr][cc+2] = t.z; xs[rr][cc+3] = t.w;
        }
        {   // W tile: 16x64, one float4 per thread
            int idx = tid * 4;
            int rr = idx >> 6;
            int cc = idx & 63;
            *(float4*)&ws[rr][cc] = *(const float4*)&W[(size_t)(kb + rr) * HH + cc];
        }
        __syncthreads();

        #pragma unroll
        for (int kk = 0; kk < 16; kk++) {
            float a[4];
            #pragma unroll
            for (int i = 0; i < 4; i++) a[i] = xs[ty*4 + i][kk];
            float4 w4 = *(const float4*)&ws[kk][tx*4];
            #pragma unroll
            for (int i = 0; i < 4; i++) {
                acc[i][0] = fmaf(a[i], w4.x, acc[i][0]);
                acc[i][1] = fmaf(a[i], w4.y, acc[i][1]);
                acc[i][2] = fmaf(a[i], w4.z, acc[i][2]);
                acc[i][3] = fmaf(a[i], w4.w, acc[i][3]);
            }
        }
        __syncthreads();
    }

    float4 b4 = *(const float4*)&bias[tx*4];
    #pragma unroll
    for (int i = 0; i < 4; i++) {
        size_t off = (size_t)(row0 + ty*4 + i) * HH + tx*4;
        *(float4*)&out[off] = make_float4(acc[i][0] + b4.x, acc[i][1] + b4.y,
                                          acc[i][2] + b4.z, acc[i][3] + b4.w);
    }
}

// ==========================================================================
// Kernel 2: split-K causal flash attention, phase 1.
// 128 threads/block; lane pair (2t, 2t+1) shares one query row, each lane
// owns 32 of the 64 head dims. Grid (qtile=32, chunk=16, batch=4).
// ==========================================================================
#define KPAD 68   // smem row stride (floats): breaks STS bank pathology

__global__ __launch_bounds__(128) void attn_partial()
{
    __shared__ float ks[64][KPAD];
    __shared__ float vs[64][KPAD];

    const int tid  = threadIdx.x;
    const int row  = tid >> 1;            // 0..63 query row within tile
    const int half = tid & 1;             // which 32 head dims this lane owns
    const int hoff = half * 32;
    const int qt   = blockIdx.x;
    const int c    = blockIdx.y;
    const int b    = blockIdx.z;

    // whole block strictly above this chunk's keys -> no work
    if (c * CH > qt * 64 + 63) return;

    const int i = qt * 64 + row;          // query position within batch
    const size_t r = (size_t)b * SS + i;  // global row

    // warp covers 16 consecutive rows starting at wrow0
    const int wrow0 = (tid >> 5) * 16;

    float qreg[32];
    #pragma unroll
    for (int e = 0; e < 32; e += 4) {
        float4 t = *(const float4*)&g_q[r * HH + hoff + e];
        qreg[e+0] = t.x; qreg[e+1] = t.y; qreg[e+2] = t.z; qreg[e+3] = t.w;
    }

    float o[32];
    #pragma unroll
    for (int e = 0; e < 32; e++) o[e] = 0.0f;
    float m = -CUDART_INF_F;
    float l = 0.0f;

    #pragma unroll 1
    for (int sub = 0; sub < 2; sub++) {
        const int k0 = c * CH + sub * 64;       // first key of sub-tile
        __syncthreads();
        {   // cooperative load: thread t fills row t/2, cols half*32..+31
            const float* kp = &g_k[((size_t)b * SS + k0 + row) * HH + hoff];
            const float* vp = &g_v[((size_t)b * SS + k0 + row) * HH + hoff];
            #pragma unroll
            for (int e = 0; e < 32; e += 4) {
                *(float4*)&ks[row][hoff + e] = *(const float4*)&kp[e];
                *(float4*)&vs[row][hoff + e] = *(const float4*)&vp[e];
            }
        }
        __syncthreads();

        const int nj_self = i - k0;                               // per-lane causal bound
        const int nj_warp = min(63, (qt*64 + wrow0 + 15) - k0);   // warp-max bound
        for (int jj = 0; jj <= nj_warp; jj++) {
            // half dot product: 32 dims, 4 partial chains
            float s0 = 0.f, s1 = 0.f, s2 = 0.f, s3 = 0.f;
            #pragma unroll
            for (int e = 0; e < 32; e += 4) {
                float4 kk4 = *(const float4*)&ks[jj][hoff + e];
                s0 = fmaf(qreg[e+0], kk4.x, s0);
                s1 = fmaf(qreg[e+1], kk4.y, s1);
                s2 = fmaf(qreg[e+2], kk4.z, s2);
                s3 = fmaf(qreg[e+3], kk4.w, s3);
            }
            float sh = (s0 + s1) + (s2 + s3);
            // combine with partner lane (full warp executes: safe full mask)
            float s = (sh + __shfl_xor_sync(0xffffffffu, sh, 1)) * 0.125f;

            if (jj <= nj_self) {
                if (s > m) {
                    float alpha = __expf(m - s);   // m=-inf on first key -> 0
                    l = l * alpha + 1.0f;
                    #pragma unroll
                    for (int e = 0; e < 32; e += 4) {
                        float4 vv = *(const float4*)&vs[jj][hoff + e];
                        o[e+0] = o[e+0] * alpha + vv.x;
                        o[e+1] = o[e+1] * alpha + vv.y;
                        o[e+2] = o[e+2] * alpha + vv.z;
                        o[e+3] = o[e+3] * alpha + vv.w;
                    }
                    m = s;
                } else {
                    float p = __expf(s - m);
                    l += p;
                    #pragma unroll
                    for (int e = 0; e < 32; e += 4) {
                        float4 vv = *(const float4*)&vs[jj][hoff + e];
                        o[e+0] = fmaf(p, vv.x, o[e+0]);
                        o[e+1] = fmaf(p, vv.y, o[e+1]);
                        o[e+2] = fmaf(p, vv.z, o[e+2]);
                        o[e+3] = fmaf(p, vv.w, o[e+3]);
                    }
                }
            }
        }
    }

    // write partials (rows with no valid keys emit m=-inf, l=0 -> never read)
    const size_t base = (r * NCH + c) * HH + hoff;
    #pragma unroll
    for (int e = 0; e < 32; e += 4)
        *(float4*)&g_opart[base + e] = make_float4(o[e], o[e+1], o[e+2], o[e+3]);
    if (half == 0) {
        g_ml[(r * NCH + c) * 2 + 0] = m;
        g_ml[(r * NCH + c) * 2 + 1] = l;
    }
}

// ==========================================================================
// Kernel 3: combine split-K partials.  One block per query row, thread = h.
// ==========================================================================
__global__ __launch_bounds__(64) void attn_combine(float* __restrict__ out)
{
    const size_t r = blockIdx.x;          // 0..8191
    const int    i = (int)(r & (SS - 1)); // position within batch
    const int    e = threadIdx.x;
    const int  nch = i / CH + 1;          // valid chunks for this row

    float M = -CUDART_INF_F;
    #pragma unroll 1
    for (int c = 0; c < nch; c++)
        M = fmaxf(M, g_ml[(r * NCH + c) * 2 + 0]);

    float L = 0.0f, o = 0.0f;
    #pragma unroll 1
    for (int c = 0; c < nch; c++) {
        float mc = g_ml[(r * NCH + c) * 2 + 0];
        float lc = g_ml[(r * NCH + c) * 2 + 1];
        float w  = __expf(mc - M);        // mc=-inf -> w=0 (empty partial)
        L += lc * w;
        o  = fmaf(w, g_opart[(r * NCH + c) * HH + e], o);
    }
    out[r * HH + e] = o / L;
}

// ==========================================================================
extern "C" void kernel_launch(void* const* d_in, const int* in_sizes, int n_in,
                              void* d_out, int out_size)
{
    const float* x  = (const float*)d_in[0];
    const float* Wq = (const float*)d_in[1];
    const float* bq = (const float*)d_in[2];
    const float* Wk = (const float*)d_in[3];
    const float* bk = (const float*)d_in[4];
    const float* Wv = (const float*)d_in[5];
    const float* bv = (const float*)d_in[6];
    float* out = (float*)d_out;

    dim3 gq(NROWS / 64, 3);
    qkv_proj<<<gq, 256>>>(x, Wq, bq, Wk, bk, Wv, bv);

    dim3 g(SS / 64, NCH, BB);
    attn_partial<<<g, 128>>>();

    attn_combine<<<NROWS, 64>>>(out);
}

// round 5
// speedup vs baseline: 1.1508x; 1.1508x over previous
#include <cuda_runtime.h>
#include <math_constants.h>
#include <cstddef>

// Problem shape (fixed by reference)
#define BB  4
#define SS  2048
#define EE  1024
#define HH  64
#define NROWS (BB*SS)     // 8192 total query rows
#define CH  64            // keys per split-K chunk (one 64x64 block)
#define NCH (SS/CH)       // 32 chunks per batch

// -------- device scratch (no allocations allowed in kernel_launch) --------
__device__ float g_q[NROWS*HH];
__device__ float g_k[NROWS*HH];
__device__ float g_v[NROWS*HH];
__device__ float g_opart[(size_t)NROWS*NCH*HH];   // unnormalized partials (67MB)
__device__ float g_ml[(size_t)NROWS*NCH*2];       // per-chunk (m, l)

// ==========================================================================
// Kernel 1: QKV projection. One matrix per blockIdx.y.
// 64 threads/block, 64x64 tile, 8x8 micro-tile per thread, BK=16.
// All smem operands consumed via LDS.128 (x staged TRANSPOSED): 1 B/FMA.
// ==========================================================================
__global__ __launch_bounds__(64) void qkv_proj(
    const float* __restrict__ x,
    const float* __restrict__ Wq, const float* __restrict__ bq,
    const float* __restrict__ Wk, const float* __restrict__ bk,
    const float* __restrict__ Wv, const float* __restrict__ bv)
{
    __shared__ float xs_t[16][64];        // transposed: [k][row]
    __shared__ float ws[16][64];          // [k][col]

    const int tid  = threadIdx.x;
    const int ry   = tid >> 3;            // 0..7 row group (8 rows each)
    const int cx   = tid & 7;             // 0..7 col group (8 cols each)
    const int row0 = blockIdx.x * 64;
    const int mat  = blockIdx.y;          // 0=Q, 1=K, 2=V

    const float* W    = (mat == 0) ? Wq : (mat == 1) ? Wk : Wv;
    const float* bias = (mat == 0) ? bq : (mat == 1) ? bk : bv;
    float* out        = (mat == 0) ? g_q : (mat == 1) ? g_k : g_v;

    float acc[8][8] = {};

    const float* xrow = &x[(size_t)(row0 + tid) * EE];

    for (int kb = 0; kb < EE; kb += 16) {
        // x tile 64x16: thread t loads its own row, stores transposed
        float4 xt[4];
        #pragma unroll
        for (int c = 0; c < 4; c++) xt[c] = *(const float4*)&xrow[kb + c*4];
        // W tile 16x64: 4 float4 per thread, row-major
        float4 wt[4];
        {
            int f0 = tid * 4;             // float4 index 0..255, 16 per row
            #pragma unroll
            for (int i = 0; i < 4; i++) {
                int f  = f0 + i;
                int rr = f >> 4;
                int cc = (f & 15) * 4;
                wt[i] = *(const float4*)&W[(size_t)(kb + rr) * HH + cc];
            }
        }
        __syncthreads();
        #pragma unroll
        for (int c = 0; c < 4; c++) {
            xs_t[c*4+0][tid] = xt[c].x;
            xs_t[c*4+1][tid] = xt[c].y;
            xs_t[c*4+2][tid] = xt[c].z;
            xs_t[c*4+3][tid] = xt[c].w;
        }
        {
            int f0 = tid * 4;
            #pragma unroll
            for (int i = 0; i < 4; i++) {
                int f  = f0 + i;
                int rr = f >> 4;
                int cc = (f & 15) * 4;
                *(float4*)&ws[rr][cc] = wt[i];
            }
        }
        __syncthreads();

        #pragma unroll 4
        for (int kk = 0; kk < 16; kk++) {
            float4 xa = *(const float4*)&xs_t[kk][ry*8];
            float4 xb = *(const float4*)&xs_t[kk][ry*8+4];
            float4 wa = *(const float4*)&ws[kk][cx*8];
            float4 wb = *(const float4*)&ws[kk][cx*8+4];
            float a[8] = {xa.x,xa.y,xa.z,xa.w, xb.x,xb.y,xb.z,xb.w};
            float w[8] = {wa.x,wa.y,wa.z,wa.w, wb.x,wb.y,wb.z,wb.w};
            #pragma unroll
            for (int i = 0; i < 8; i++)
                #pragma unroll
                for (int j = 0; j < 8; j++)
                    acc[i][j] = fmaf(a[i], w[j], acc[i][j]);
        }
        __syncthreads();
    }

    float4 b4a = *(const float4*)&bias[cx*8];
    float4 b4b = *(const float4*)&bias[cx*8+4];
    float bb[8] = {b4a.x,b4a.y,b4a.z,b4a.w, b4b.x,b4b.y,b4b.z,b4b.w};

    #pragma unroll
    for (int i = 0; i < 8; i++) {
        size_t off = (size_t)(row0 + ry*8 + i) * HH + cx*8;
        *(float4*)&out[off]   = make_float4(acc[i][0]+bb[0], acc[i][1]+bb[1],
                                            acc[i][2]+bb[2], acc[i][3]+bb[3]);
        *(float4*)&out[off+4] = make_float4(acc[i][4]+bb[4], acc[i][5]+bb[5],
                                            acc[i][6]+bb[6], acc[i][7]+bb[7]);
    }
}

// ==========================================================================
// Kernel 2: split-K causal attention, one 64q x 64k block per CTA.
// 64 threads, two register-tiled GEMMs (8x8 micro), shfl row softmax.
// Smem: Qt/Kt (Phase A) overlaid with Ps (Phase B) via union -> 32KB total.
// Grid (qt=32, c=32, b=4), early exit if c > qt (strictly above diagonal).
// ==========================================================================
struct SmemQK { float Qt[HH][64]; float Kt[HH][64]; };   // 32 KB
struct SmemP  { float Ps[64][68]; };                     // 17.4 KB

__global__ __launch_bounds__(64) void attn_partial()
{
    __shared__ union { SmemQK qk; SmemP p; } sm;

    const int tid = threadIdx.x;
    const int qt  = blockIdx.x;
    const int c   = blockIdx.y;
    const int b   = blockIdx.z;
    if (c > qt) return;

    const int q0 = qt * 64;
    const int k0 = c * 64;
    const bool diag = (c == qt);

    // stage Q (scaled) and K transposed: thread t owns one row
    {
        const float* qrow = &g_q[((size_t)b*SS + q0 + tid) * HH];
        const float* krow = &g_k[((size_t)b*SS + k0 + tid) * HH];
        #pragma unroll
        for (int e = 0; e < HH; e += 4) {
            float4 qv = *(const float4*)&qrow[e];
            float4 kv = *(const float4*)&krow[e];
            sm.qk.Qt[e+0][tid] = qv.x * 0.125f;  // fold 1/sqrt(64)
            sm.qk.Qt[e+1][tid] = qv.y * 0.125f;
            sm.qk.Qt[e+2][tid] = qv.z * 0.125f;
            sm.qk.Qt[e+3][tid] = qv.w * 0.125f;
            sm.qk.Kt[e+0][tid] = kv.x;
            sm.qk.Kt[e+1][tid] = kv.y;
            sm.qk.Kt[e+2][tid] = kv.z;
            sm.qk.Kt[e+3][tid] = kv.w;
        }
    }
    __syncthreads();

    const int qg = tid >> 3;              // 0..7: rows qg*8..+7
    const int kg = tid & 7;               // 0..7: cols kg*8..+7

    // ---- Phase A: S = Q K^T ----
    float S[8][8] = {};
    #pragma unroll 4
    for (int e = 0; e < HH; e++) {
        float4 qa = *(const float4*)&sm.qk.Qt[e][qg*8];
        float4 qb = *(const float4*)&sm.qk.Qt[e][qg*8+4];
        float4 ka = *(const float4*)&sm.qk.Kt[e][kg*8];
        float4 kb = *(const float4*)&sm.qk.Kt[e][kg*8+4];
        float qv[8] = {qa.x,qa.y,qa.z,qa.w, qb.x,qb.y,qb.z,qb.w};
        float kv[8] = {ka.x,ka.y,ka.z,ka.w, kb.x,kb.y,kb.z,kb.w};
        #pragma unroll
        for (int i = 0; i < 8; i++)
            #pragma unroll
            for (int j = 0; j < 8; j++)
                S[i][j] = fmaf(qv[i], kv[j], S[i][j]);
    }

    // ---- softmax over each row (across kg lanes via shfl) ----
    float m8[8], l8[8];
    #pragma unroll
    for (int qi = 0; qi < 8; qi++) {
        const int iq = qg*8 + qi;         // local query index
        float mx = -CUDART_INF_F;
        #pragma unroll
        for (int ji = 0; ji < 8; ji++) {
            float s = S[qi][ji];
            if (diag && (kg*8 + ji > iq)) s = -CUDART_INF_F;
            S[qi][ji] = s;
            mx = fmaxf(mx, s);
        }
        mx = fmaxf(mx, __shfl_xor_sync(0xffffffffu, mx, 1));
        mx = fmaxf(mx, __shfl_xor_sync(0xffffffffu, mx, 2));
        mx = fmaxf(mx, __shfl_xor_sync(0xffffffffu, mx, 4));
        float sum = 0.0f;
        #pragma unroll
        for (int ji = 0; ji < 8; ji++) {
            float p = __expf(S[qi][ji] - mx);   // exp(-inf)=0 on masked
            S[qi][ji] = p;
            sum += p;
        }
        sum += __shfl_xor_sync(0xffffffffu, sum, 1);
        sum += __shfl_xor_sync(0xffffffffu, sum, 2);
        sum += __shfl_xor_sync(0xffffffffu, sum, 4);
        m8[qi] = mx;
        l8[qi] = sum;
    }

    // write (m,l) once per row
    if (kg == 0) {
        #pragma unroll
        for (int qi = 0; qi < 8; qi++) {
            size_t r = (size_t)b*SS + q0 + qg*8 + qi;
            g_ml[(r*NCH + c)*2 + 0] = m8[qi];
            g_ml[(r*NCH + c)*2 + 1] = l8[qi];
        }
    }

    // Qt/Kt dead from here; make sure every thread finished Phase A reads
    // before Ps overwrites the same bytes.
    __syncthreads();

    // stage P to smem
    #pragma unroll
    for (int qi = 0; qi < 8; qi++) {
        *(float4*)&sm.p.Ps[qg*8+qi][kg*8]   = make_float4(S[qi][0],S[qi][1],S[qi][2],S[qi][3]);
        *(float4*)&sm.p.Ps[qg*8+qi][kg*8+4] = make_float4(S[qi][4],S[qi][5],S[qi][6],S[qi][7]);
    }
    __syncthreads();

    // ---- Phase B: O = P V  (V streamed from gmem, broadcast-coalesced) ----
    const int hg = kg;                    // cols hg*8..+7 of head dim
    float O[8][8] = {};
    const float* vbase = &g_v[((size_t)b*SS + k0) * HH + hg*8];

    #pragma unroll 2
    for (int j0 = 0; j0 < 64; j0 += 4) {
        float4 va[4], vb[4];
        #pragma unroll
        for (int jj = 0; jj < 4; jj++) {
            va[jj] = *(const float4*)&vbase[(size_t)(j0+jj)*HH];
            vb[jj] = *(const float4*)&vbase[(size_t)(j0+jj)*HH + 4];
        }
        #pragma unroll
        for (int qi = 0; qi < 8; qi++) {
            float4 p4 = *(const float4*)&sm.p.Ps[qg*8+qi][j0];
            float pv[4] = {p4.x, p4.y, p4.z, p4.w};
            #pragma unroll
            for (int jj = 0; jj < 4; jj++) {
                O[qi][0] = fmaf(pv[jj], va[jj].x, O[qi][0]);
                O[qi][1] = fmaf(pv[jj], va[jj].y, O[qi][1]);
                O[qi][2] = fmaf(pv[jj], va[jj].z, O[qi][2]);
                O[qi][3] = fmaf(pv[jj], va[jj].w, O[qi][3]);
                O[qi][4] = fmaf(pv[jj], vb[jj].x, O[qi][4]);
                O[qi][5] = fmaf(pv[jj], vb[jj].y, O[qi][5]);
                O[qi][6] = fmaf(pv[jj], vb[jj].z, O[qi][6]);
                O[qi][7] = fmaf(pv[jj], vb[jj].w, O[qi][7]);
            }
        }
    }

    // write unnormalized partials
    #pragma unroll
    for (int qi = 0; qi < 8; qi++) {
        size_t r = (size_t)b*SS + q0 + qg*8 + qi;
        size_t base = (r*NCH + c)*HH + hg*8;
        *(float4*)&g_opart[base]   = make_float4(O[qi][0],O[qi][1],O[qi][2],O[qi][3]);
        *(float4*)&g_opart[base+4] = make_float4(O[qi][4],O[qi][5],O[qi][6],O[qi][7]);
    }
}

// ==========================================================================
// Kernel 3: combine split-K partials. One block per query row, thread = h.
// ==========================================================================
__global__ __launch_bounds__(64) void attn_combine(float* __restrict__ out)
{
    const size_t r = blockIdx.x;          // 0..8191
    const int    i = (int)(r & (SS - 1)); // position within batch
    const int    e = threadIdx.x;
    const int  nch = i / CH + 1;          // valid chunks for this row

    float M = -CUDART_INF_F;
    #pragma unroll 1
    for (int c = 0; c < nch; c++)
        M = fmaxf(M, g_ml[(r * NCH + c) * 2 + 0]);

    float L = 0.0f, o = 0.0f;
    #pragma unroll 1
    for (int c = 0; c < nch; c++) {
        float mc = g_ml[(r * NCH + c) * 2 + 0];
        float lc = g_ml[(r * NCH + c) * 2 + 1];
        float w  = __expf(mc - M);
        L += lc * w;
        o  = fmaf(w, g_opart[(r * NCH + c) * HH + e], o);
    }
    out[r * HH + e] = o / L;
}

// ==========================================================================
extern "C" void kernel_launch(void* const* d_in, const int* in_sizes, int n_in,
                              void* d_out, int out_size)
{
    const float* x  = (const float*)d_in[0];
    const float* Wq = (const float*)d_in[1];
    const float* bq = (const float*)d_in[2];
    const float* Wk = (const float*)d_in[3];
    const float* bk = (const float*)d_in[4];
    const float* Wv = (const float*)d_in[5];
    const float* bv = (const float*)d_in[6];
    float* out = (float*)d_out;

    dim3 gq(NROWS / 64, 3);
    qkv_proj<<<gq, 64>>>(x, Wq, bq, Wk, bk, Wv, bv);

    dim3 ga(SS / 64, SS / 64, BB);        // early-exit above diagonal
    attn_partial<<<ga, 64>>>();

    attn_combine<<<NROWS, 64>>>(out);
}

// round 6
// speedup vs baseline: 2.4768x; 2.1522x over previous
#include <cuda_runtime.h>
#include <math_constants.h>
#include <cstdint>
#include <cstddef>

// Problem shape (fixed by reference)
#define BB  4
#define SS  2048
#define EE  1024
#define HH  64
#define NROWS (BB*SS)     // 8192 query rows
#define CH  128           // keys per split-K chunk (two 64-key subtiles)
#define NCH (SS/CH)       // 16 chunks per batch

// -------- device scratch (no allocations allowed) --------
__device__ float g_q[NROWS*HH];
__device__ float g_k[NROWS*HH];
__device__ float g_v[NROWS*HH];
__device__ float g_opart[(size_t)NROWS*NCH*HH];   // unnormalized partials (33.5MB)
__device__ float g_ml[(size_t)NROWS*NCH*2];       // per-chunk (m, l)

// -------- tf32 helpers --------
__device__ __forceinline__ float tf32r(float x) {
    uint32_t u;
    asm("cvt.rna.tf32.f32 %0, %1;" : "=r"(u) : "f"(x));
    return __uint_as_float(u);
}
// D += A(16x8) * B(8x8), tf32 inputs, fp32 accumulate
__device__ __forceinline__ void mma_tf32(float* d, const uint32_t* a, const uint32_t* b) {
    asm volatile(
        "mma.sync.aligned.m16n8k8.row.col.f32.tf32.tf32.f32 "
        "{%0,%1,%2,%3}, {%4,%5,%6,%7}, {%8,%9}, {%0,%1,%2,%3};"
        : "+f"(d[0]), "+f"(d[1]), "+f"(d[2]), "+f"(d[3])
        : "r"(a[0]), "r"(a[1]), "r"(a[2]), "r"(a[3]), "r"(b[0]), "r"(b[1]));
}

// ==========================================================================
// Kernel 1: QKV projection with tf32 tensor-core mma.
// Block 128 threads (4 warps). Tile M=128, N=64, BK=32.
// Warp owns 32 rows (2 m-tiles of 16). Grid (8192/128, 3).
// ==========================================================================
#define XS_ST 36   // 32 + 4 pad: conflict-free A-frag LDS
#define WS_ST 68   // 64 + 4 pad: conflict-free B-frag LDS

__global__ __launch_bounds__(128) void qkv_proj(
    const float* __restrict__ x,
    const float* __restrict__ Wq, const float* __restrict__ bq,
    const float* __restrict__ Wk, const float* __restrict__ bk,
    const float* __restrict__ Wv, const float* __restrict__ bv)
{
    __shared__ float xs[128*XS_ST];       // 18.4 KB
    __shared__ float ws[32*WS_ST];        // 8.7 KB

    const int tid  = threadIdx.x;
    const int warp = tid >> 5;
    const int lane = tid & 31;
    const int g    = lane >> 2;           // groupID 0..7
    const int tig  = lane & 3;            // thread-in-group 0..3
    const int row0 = blockIdx.x * 128;
    const int mat  = blockIdx.y;

    const float* W    = (mat == 0) ? Wq : (mat == 1) ? Wk : Wv;
    const float* bias = (mat == 0) ? bq : (mat == 1) ? bk : bv;
    float* out        = (mat == 0) ? g_q : (mat == 1) ? g_k : g_v;

    float acc[2][8][4] = {};

    for (int kb = 0; kb < EE; kb += 32) {
        // stage x tile 128x32 (tf32-rounded)
        #pragma unroll
        for (int i = 0; i < 8; i++) {
            int f4 = i*128 + tid;
            int r = f4 >> 3, c4 = f4 & 7;
            float4 t = *(const float4*)&x[(size_t)(row0 + r)*EE + kb + c4*4];
            float* p = &xs[r*XS_ST + c4*4];
            p[0]=tf32r(t.x); p[1]=tf32r(t.y); p[2]=tf32r(t.z); p[3]=tf32r(t.w);
        }
        // stage W tile 32x64 (tf32-rounded)
        #pragma unroll
        for (int i = 0; i < 4; i++) {
            int f4 = i*128 + tid;
            int r = f4 >> 4, c4 = f4 & 15;
            float4 t = *(const float4*)&W[(size_t)(kb + r)*HH + c4*4];
            float* p = &ws[r*WS_ST + c4*4];
            p[0]=tf32r(t.x); p[1]=tf32r(t.y); p[2]=tf32r(t.z); p[3]=tf32r(t.w);
        }
        __syncthreads();

        #pragma unroll
        for (int ks = 0; ks < 4; ks++) {
            const int kc = ks * 8;
            uint32_t bf[8][2];
            #pragma unroll
            for (int nt = 0; nt < 8; nt++) {
                bf[nt][0] = __float_as_uint(ws[(kc+tig  )*WS_ST + nt*8 + g]);
                bf[nt][1] = __float_as_uint(ws[(kc+tig+4)*WS_ST + nt*8 + g]);
            }
            #pragma unroll
            for (int mt = 0; mt < 2; mt++) {
                const int rb = warp*32 + mt*16 + g;
                uint32_t a[4];
                a[0] = __float_as_uint(xs[ rb   *XS_ST + kc + tig    ]);
                a[1] = __float_as_uint(xs[(rb+8)*XS_ST + kc + tig    ]);
                a[2] = __float_as_uint(xs[ rb   *XS_ST + kc + tig + 4]);
                a[3] = __float_as_uint(xs[(rb+8)*XS_ST + kc + tig + 4]);
                #pragma unroll
                for (int nt = 0; nt < 8; nt++)
                    mma_tf32(acc[mt][nt], a, bf[nt]);
            }
        }
        __syncthreads();
    }

    #pragma unroll
    for (int mt = 0; mt < 2; mt++) {
        #pragma unroll
        for (int nt = 0; nt < 8; nt++) {
            const int row = row0 + warp*32 + mt*16 + g;
            const int col = nt*8 + 2*tig;
            const float b0 = __ldg(&bias[col]);
            const float b1 = __ldg(&bias[col+1]);
            float2 v0 = make_float2(acc[mt][nt][0] + b0, acc[mt][nt][1] + b1);
            float2 v1 = make_float2(acc[mt][nt][2] + b0, acc[mt][nt][3] + b1);
            *(float2*)&out[(size_t) row   *HH + col] = v0;
            *(float2*)&out[(size_t)(row+8)*HH + col] = v1;
        }
    }
}

// ==========================================================================
// Kernel 2: split-K causal flash attention in tensor-core fragments.
// Block = 128 threads (4 warps); block handles 64 q-rows x 128 keys
// (two 64-key subtiles with in-register online rescale).
// Dynamic smem: Qs | KP (Kt, overlaid by Ps) | Vs, each 64x68 floats.
// Grid (qt=32, c=16, b=4); active iff 2c <= qt.
// ==========================================================================
#define AST 68
#define ATTN_SMEM (3*64*AST*4)

__global__ __launch_bounds__(128) void attn_partial()
{
    extern __shared__ float dsm[];
    float* Qs = dsm;                      // [q][e], scaled, tf32
    float* KP = dsm + 64*AST;             // Kt [e][k] -> Ps [q][k]
    float* Vs = dsm + 2*64*AST;           // [k][h]

    const int tid  = threadIdx.x;
    const int warp = tid >> 5;
    const int lane = tid & 31;
    const int g    = lane >> 2;
    const int tig  = lane & 3;
    const int qt   = blockIdx.x;
    const int c    = blockIdx.y;
    const int b    = blockIdx.z;
    if (2*c > qt) return;

    const int q0 = qt * 64;
    const int wq = warp * 16;             // warp's q offset in tile

    // stage Q (scaled by 1/8, tf32-rounded)
    #pragma unroll
    for (int i = 0; i < 8; i++) {
        int f4 = i*128 + tid;
        int r = f4 >> 4, c4 = f4 & 15;
        float4 t = *(const float4*)&g_q[((size_t)b*SS + q0 + r)*HH + c4*4];
        float* p = &Qs[r*AST + c4*4];
        p[0]=tf32r(t.x*0.125f); p[1]=tf32r(t.y*0.125f);
        p[2]=tf32r(t.z*0.125f); p[3]=tf32r(t.w*0.125f);
    }

    float O[8][4] = {};
    float m0 = -CUDART_INF_F, m1 = -CUDART_INF_F;
    float l0 = 0.0f, l1 = 0.0f;

    #pragma unroll 1
    for (int sub = 0; sub < 2; sub++) {
        const int k0 = c*CH + sub*64;
        if (k0 > q0) break;               // subtile entirely above diagonal
        const bool diag = (k0 == q0);

        __syncthreads();                  // Qs visible / prior Phase B done
        // stage Kt transposed [e][k] (2 threads per key row)
        {
            const int kr = tid >> 1, half = tid & 1;
            const float* kp = &g_k[((size_t)b*SS + k0 + kr)*HH + half*32];
            #pragma unroll
            for (int i = 0; i < 8; i++) {
                float4 t = *(const float4*)&kp[i*4];
                int e = half*32 + i*4;
                KP[(e+0)*AST + kr] = tf32r(t.x);
                KP[(e+1)*AST + kr] = tf32r(t.y);
                KP[(e+2)*AST + kr] = tf32r(t.z);
                KP[(e+3)*AST + kr] = tf32r(t.w);
            }
        }
        // stage V [k][h]
        #pragma unroll
        for (int i = 0; i < 8; i++) {
            int f4 = i*128 + tid;
            int r = f4 >> 4, c4 = f4 & 15;
            float4 t = *(const float4*)&g_v[((size_t)b*SS + k0 + r)*HH + c4*4];
            float* p = &Vs[r*AST + c4*4];
            p[0]=tf32r(t.x); p[1]=tf32r(t.y); p[2]=tf32r(t.z); p[3]=tf32r(t.w);
        }
        __syncthreads();

        // ---- Phase A: S = Qhat Khat^T ----
        float S[8][4] = {};
        #pragma unroll
        for (int ks = 0; ks < 8; ks++) {
            const int kc = ks * 8;
            uint32_t a[4];
            a[0] = __float_as_uint(Qs[(wq+g  )*AST + kc + tig    ]);
            a[1] = __float_as_uint(Qs[(wq+g+8)*AST + kc + tig    ]);
            a[2] = __float_as_uint(Qs[(wq+g  )*AST + kc + tig + 4]);
            a[3] = __float_as_uint(Qs[(wq+g+8)*AST + kc + tig + 4]);
            #pragma unroll
            for (int nt = 0; nt < 8; nt++) {
                uint32_t bf[2];
                bf[0] = __float_as_uint(KP[(kc+tig  )*AST + nt*8 + g]);
                bf[1] = __float_as_uint(KP[(kc+tig+4)*AST + nt*8 + g]);
                mma_tf32(S[nt], a, bf);
            }
        }

        // ---- causal mask (diagonal subtile only) ----
        const int gq0 = q0 + wq + g;      // row of c0/c1
        const int gq1 = gq0 + 8;          // row of c2/c3
        if (diag) {
            #pragma unroll
            for (int nt = 0; nt < 8; nt++) {
                const int kc = k0 + nt*8 + 2*tig;
                if (kc   > gq0) S[nt][0] = -CUDART_INF_F;
                if (kc+1 > gq0) S[nt][1] = -CUDART_INF_F;
                if (kc   > gq1) S[nt][2] = -CUDART_INF_F;
                if (kc+1 > gq1) S[nt][3] = -CUDART_INF_F;
            }
        }

        // ---- online softmax over rows (quad shfl) ----
        float mx0 = -CUDART_INF_F, mx1 = -CUDART_INF_F;
        #pragma unroll
        for (int nt = 0; nt < 8; nt++) {
            mx0 = fmaxf(mx0, fmaxf(S[nt][0], S[nt][1]));
            mx1 = fmaxf(mx1, fmaxf(S[nt][2], S[nt][3]));
        }
        mx0 = fmaxf(mx0, __shfl_xor_sync(0xffffffffu, mx0, 1));
        mx0 = fmaxf(mx0, __shfl_xor_sync(0xffffffffu, mx0, 2));
        mx1 = fmaxf(mx1, __shfl_xor_sync(0xffffffffu, mx1, 1));
        mx1 = fmaxf(mx1, __shfl_xor_sync(0xffffffffu, mx1, 2));

        const float nm0 = fmaxf(m0, mx0), nm1 = fmaxf(m1, mx1);
        const float al0 = __expf(m0 - nm0), al1 = __expf(m1 - nm1);
        m0 = nm0; m1 = nm1;

        float s0 = 0.0f, s1 = 0.0f;
        #pragma unroll
        for (int nt = 0; nt < 8; nt++) {
            S[nt][0] = __expf(S[nt][0] - nm0);
            S[nt][1] = __expf(S[nt][1] - nm0);
            S[nt][2] = __expf(S[nt][2] - nm1);
            S[nt][3] = __expf(S[nt][3] - nm1);
            s0 += S[nt][0] + S[nt][1];
            s1 += S[nt][2] + S[nt][3];
        }
        s0 += __shfl_xor_sync(0xffffffffu, s0, 1);
        s0 += __shfl_xor_sync(0xffffffffu, s0, 2);
        s1 += __shfl_xor_sync(0xffffffffu, s1, 1);
        s1 += __shfl_xor_sync(0xffffffffu, s1, 2);
        l0 = l0*al0 + s0;
        l1 = l1*al1 + s1;
        #pragma unroll
        for (int nt = 0; nt < 8; nt++) {
            O[nt][0] *= al0; O[nt][1] *= al0;
            O[nt][2] *= al1; O[nt][3] *= al1;
        }

        __syncthreads();                  // everyone done reading Kt
        // stage P (tf32) over the Kt region
        #pragma unroll
        for (int nt = 0; nt < 8; nt++) {
            *(float2*)&KP[(wq+g  )*AST + nt*8 + 2*tig] =
                make_float2(tf32r(S[nt][0]), tf32r(S[nt][1]));
            *(float2*)&KP[(wq+g+8)*AST + nt*8 + 2*tig] =
                make_float2(tf32r(S[nt][2]), tf32r(S[nt][3]));
        }
        __syncthreads();

        // ---- Phase B: O += P V ----
        #pragma unroll
        for (int ks = 0; ks < 8; ks++) {
            const int kc = ks * 8;
            uint32_t a[4];
            a[0] = __float_as_uint(KP[(wq+g  )*AST + kc + tig    ]);
            a[1] = __float_as_uint(KP[(wq+g+8)*AST + kc + tig    ]);
            a[2] = __float_as_uint(KP[(wq+g  )*AST + kc + tig + 4]);
            a[3] = __float_as_uint(KP[(wq+g+8)*AST + kc + tig + 4]);
            #pragma unroll
            for (int nt = 0; nt < 8; nt++) {
                uint32_t bf[2];
                bf[0] = __float_as_uint(Vs[(kc+tig  )*AST + nt*8 + g]);
                bf[1] = __float_as_uint(Vs[(kc+tig+4)*AST + nt*8 + g]);
                mma_tf32(O[nt], a, bf);
            }
        }
    }

    // ---- write unnormalized partials + (m, l) ----
    const size_t r0 = (size_t)b*SS + q0 + wq + g;
    const size_t r1 = r0 + 8;
    #pragma unroll
    for (int nt = 0; nt < 8; nt++) {
        const int col = nt*8 + 2*tig;
        *(float2*)&g_opart[(r0*NCH + c)*HH + col] = make_float2(O[nt][0], O[nt][1]);
        *(float2*)&g_opart[(r1*NCH + c)*HH + col] = make_float2(O[nt][2], O[nt][3]);
    }
    if (tig == 0) {
        g_ml[(r0*NCH + c)*2 + 0] = m0;
        g_ml[(r0*NCH + c)*2 + 1] = l0;
        g_ml[(r1*NCH + c)*2 + 0] = m1;
        g_ml[(r1*NCH + c)*2 + 1] = l1;
    }
}

// ==========================================================================
// Kernel 3: combine split-K partials. One block per query row, thread = h.
// ==========================================================================
__global__ __launch_bounds__(64) void attn_combine(float* __restrict__ out)
{
    const size_t r = blockIdx.x;          // 0..8191
    const int    i = (int)(r & (SS - 1)); // position within batch
    const int    e = threadIdx.x;
    const int  nch = i / CH + 1;          // valid chunks for this row

    float M = -CUDART_INF_F;
    #pragma unroll 1
    for (int c = 0; c < nch; c++)
        M = fmaxf(M, g_ml[(r * NCH + c) * 2 + 0]);

    float L = 0.0f, o = 0.0f;
    #pragma unroll 1
    for (int c = 0; c < nch; c++) {
        float mc = g_ml[(r * NCH + c) * 2 + 0];
        float lc = g_ml[(r * NCH + c) * 2 + 1];
        float w  = __expf(mc - M);
        L += lc * w;
        o  = fmaf(w, g_opart[(r * NCH + c) * HH + e], o);
    }
    out[r * HH + e] = o / L;
}

// ==========================================================================
extern "C" void kernel_launch(void* const* d_in, const int* in_sizes, int n_in,
                              void* d_out, int out_size)
{
    const float* x  = (const float*)d_in[0];
    const float* Wq = (const float*)d_in[1];
    const float* bq = (const float*)d_in[2];
    const float* Wk = (const float*)d_in[3];
    const float* bk = (const float*)d_in[4];
    const float* Wv = (const float*)d_in[5];
    const float* bv = (const float*)d_in[6];
    float* out = (float*)d_out;

    cudaFuncSetAttribute(attn_partial,
                         cudaFuncAttributeMaxDynamicSharedMemorySize, ATTN_SMEM);

    dim3 gq(NROWS / 128, 3);
    qkv_proj<<<gq, 128>>>(x, Wq, bq, Wk, bk, Wv, bv);

    dim3 ga(SS / 64, NCH, BB);            // active iff 2c <= qt
    attn_partial<<<ga, 128, ATTN_SMEM>>>();

    attn_combine<<<NROWS, 64>>>(out);
}

// round 7
// speedup vs baseline: 2.6669x; 1.0768x over previous
#include <cuda_runtime.h>
#include <math_constants.h>
#include <cstdint>
#include <cstddef>

// Problem shape (fixed by reference)
#define BB  4
#define SS  2048
#define EE  1024
#define HH  64
#define NROWS (BB*SS)     // 8192 query rows
#define CH  256           // keys per split-K chunk (four 64-key subtiles)
#define NCH (SS/CH)       // 8 chunks per batch

// -------- device scratch (no allocations allowed) --------
__device__ float g_q[NROWS*HH];
__device__ float g_k[NROWS*HH];
__device__ float g_v[NROWS*HH];
__device__ float g_opart[(size_t)NROWS*NCH*HH];   // unnormalized partials (16.7MB)
__device__ float g_ml[(size_t)NROWS*NCH*2];       // per-chunk (m, l)

// -------- tf32 helpers --------
__device__ __forceinline__ float tf32r(float x) {
    uint32_t u;
    asm("cvt.rna.tf32.f32 %0, %1;" : "=r"(u) : "f"(x));
    return __uint_as_float(u);
}
// D += A(16x8) * B(8x8), tf32 inputs, fp32 accumulate
__device__ __forceinline__ void mma_tf32(float* d, const uint32_t* a, const uint32_t* b) {
    asm volatile(
        "mma.sync.aligned.m16n8k8.row.col.f32.tf32.tf32.f32 "
        "{%0,%1,%2,%3}, {%4,%5,%6,%7}, {%8,%9}, {%0,%1,%2,%3};"
        : "+f"(d[0]), "+f"(d[1]), "+f"(d[2]), "+f"(d[3])
        : "r"(a[0]), "r"(a[1]), "r"(a[2]), "r"(a[3]), "r"(b[0]), "r"(b[1]));
}

// ==========================================================================
// Kernel 1: QKV projection, tf32 mma, software-pipelined global loads.
// Block 256 threads (8 warps). Tile M=128, N=64, BK=32; warp owns one
// 16-row m-tile. Grid (8192/128, 3) = 192 blocks, ~80 regs/thread.
// ==========================================================================
#define XS_ST 36   // 32 + 4 pad: conflict-free A-frag LDS
#define WS_ST 68   // 64 + 4 pad: conflict-free B-frag LDS

__global__ __launch_bounds__(256) void qkv_proj(
    const float* __restrict__ x,
    const float* __restrict__ Wq, const float* __restrict__ bq,
    const float* __restrict__ Wk, const float* __restrict__ bk,
    const float* __restrict__ Wv, const float* __restrict__ bv)
{
    __shared__ float xs[128*XS_ST];       // 18.4 KB
    __shared__ float ws[32*WS_ST];        // 8.7 KB

    const int tid  = threadIdx.x;
    const int warp = tid >> 5;
    const int lane = tid & 31;
    const int g    = lane >> 2;           // groupID 0..7
    const int tig  = lane & 3;            // thread-in-group 0..3
    const int row0 = blockIdx.x * 128;
    const int mat  = blockIdx.y;

    const float* W    = (mat == 0) ? Wq : (mat == 1) ? Wk : Wv;
    const float* bias = (mat == 0) ? bq : (mat == 1) ? bk : bv;
    float* out        = (mat == 0) ? g_q : (mat == 1) ? g_k : g_v;

    float4 xt[2];   // x tile prefetch: 128x32 / 256 thr = 2 float4 each... (see below)
    float4 xt2[2];
    float4 wt[2];

    // x tile: 128 rows x 32 cols = 1024 float4, 4 per thread
    // W tile: 32 rows x 64 cols  = 512 float4,  2 per thread
    auto load_x = [&](int kb, float4* t) {
        #pragma unroll
        for (int i = 0; i < 2; i++) {
            int f4 = i*256 + tid;
            int r = f4 >> 3, c4 = f4 & 7;
            t[i] = *(const float4*)&x[(size_t)(row0 + r)*EE + kb + c4*4];
        }
    };
    auto load_x2 = [&](int kb, float4* t) {
        #pragma unroll
        for (int i = 0; i < 2; i++) {
            int f4 = (i+2)*256 + tid;
            int r = f4 >> 3, c4 = f4 & 7;
            t[i] = *(const float4*)&x[(size_t)(row0 + r)*EE + kb + c4*4];
        }
    };
    auto load_w = [&](int kb, float4* t) {
        #pragma unroll
        for (int i = 0; i < 2; i++) {
            int f4 = i*256 + tid;
            int r = f4 >> 4, c4 = f4 & 15;
            t[i] = *(const float4*)&W[(size_t)(kb + r)*HH + c4*4];
        }
    };

    load_x(0, xt); load_x2(0, xt2); load_w(0, wt);

    float acc[8][4] = {};

    #pragma unroll 1
    for (int kb = 0; kb < EE; kb += 32) {
        // stage prefetched tiles to smem (tf32-rounded)
        #pragma unroll
        for (int i = 0; i < 2; i++) {
            int f4 = i*256 + tid;
            int r = f4 >> 3, c4 = f4 & 7;
            float* p = &xs[r*XS_ST + c4*4];
            p[0]=tf32r(xt[i].x); p[1]=tf32r(xt[i].y);
            p[2]=tf32r(xt[i].z); p[3]=tf32r(xt[i].w);
        }
        #pragma unroll
        for (int i = 0; i < 2; i++) {
            int f4 = (i+2)*256 + tid;
            int r = f4 >> 3, c4 = f4 & 7;
            float* p = &xs[r*XS_ST + c4*4];
            p[0]=tf32r(xt2[i].x); p[1]=tf32r(xt2[i].y);
            p[2]=tf32r(xt2[i].z); p[3]=tf32r(xt2[i].w);
        }
        #pragma unroll
        for (int i = 0; i < 2; i++) {
            int f4 = i*256 + tid;
            int r = f4 >> 4, c4 = f4 & 15;
            float* p = &ws[r*WS_ST + c4*4];
            p[0]=tf32r(wt[i].x); p[1]=tf32r(wt[i].y);
            p[2]=tf32r(wt[i].z); p[3]=tf32r(wt[i].w);
        }
        __syncthreads();

        // issue next tile's global loads; they fly during the MMAs below
        if (kb + 32 < EE) {
            load_x(kb+32, xt); load_x2(kb+32, xt2); load_w(kb+32, wt);
        }

        #pragma unroll
        for (int ks = 0; ks < 4; ks++) {
            const int kc = ks * 8;
            const int rb = warp*16 + g;
            uint32_t a[4];
            a[0] = __float_as_uint(xs[ rb   *XS_ST + kc + tig    ]);
            a[1] = __float_as_uint(xs[(rb+8)*XS_ST + kc + tig    ]);
            a[2] = __float_as_uint(xs[ rb   *XS_ST + kc + tig + 4]);
            a[3] = __float_as_uint(xs[(rb+8)*XS_ST + kc + tig + 4]);
            #pragma unroll
            for (int nt = 0; nt < 8; nt++) {
                uint32_t bf[2];
                bf[0] = __float_as_uint(ws[(kc+tig  )*WS_ST + nt*8 + g]);
                bf[1] = __float_as_uint(ws[(kc+tig+4)*WS_ST + nt*8 + g]);
                mma_tf32(acc[nt], a, bf);
            }
        }
        __syncthreads();
    }

    #pragma unroll
    for (int nt = 0; nt < 8; nt++) {
        const int row = row0 + warp*16 + g;
        const int col = nt*8 + 2*tig;
        const float b0 = __ldg(&bias[col]);
        const float b1 = __ldg(&bias[col+1]);
        *(float2*)&out[(size_t) row   *HH + col] =
            make_float2(acc[nt][0] + b0, acc[nt][1] + b1);
        *(float2*)&out[(size_t)(row+8)*HH + col] =
            make_float2(acc[nt][2] + b0, acc[nt][3] + b1);
    }
}

// ==========================================================================
// Kernel 2: split-K causal flash attention in tensor-core fragments.
// Block = 128 threads (4 warps); 64 q-rows x 256 keys (four 64-key
// subtiles, in-register online rescale).
// Dynamic smem: Qs | KP (Kt overlaid by Ps) | Vs, each 64x68 floats.
// Grid (qt=32, c=8, b=4); active iff 4c <= qt.
// ==========================================================================
#define AST 68
#define ATTN_SMEM (3*64*AST*4)

__global__ __launch_bounds__(128) void attn_partial()
{
    extern __shared__ float dsm[];
    float* Qs = dsm;                      // [q][e], scaled, tf32
    float* KP = dsm + 64*AST;             // Kt [e][k] -> Ps [q][k]
    float* Vs = dsm + 2*64*AST;           // [k][h]

    const int tid  = threadIdx.x;
    const int warp = tid >> 5;
    const int lane = tid & 31;
    const int g    = lane >> 2;
    const int tig  = lane & 3;
    const int qt   = blockIdx.x;
    const int c    = blockIdx.y;
    const int b    = blockIdx.z;
    if (4*c > qt) return;

    const int q0 = qt * 64;
    const int wq = warp * 16;             // warp's q offset in tile

    // stage Q (scaled by 1/8, tf32-rounded)
    #pragma unroll
    for (int i = 0; i < 8; i++) {
        int f4 = i*128 + tid;
        int r = f4 >> 4, c4 = f4 & 15;
        float4 t = *(const float4*)&g_q[((size_t)b*SS + q0 + r)*HH + c4*4];
        float* p = &Qs[r*AST + c4*4];
        p[0]=tf32r(t.x*0.125f); p[1]=tf32r(t.y*0.125f);
        p[2]=tf32r(t.z*0.125f); p[3]=tf32r(t.w*0.125f);
    }

    float O[8][4] = {};
    float m0 = -CUDART_INF_F, m1 = -CUDART_INF_F;
    float l0 = 0.0f, l1 = 0.0f;

    #pragma unroll 1
    for (int sub = 0; sub < 4; sub++) {
        const int k0 = c*CH + sub*64;
        if (k0 > q0) break;               // subtile entirely above diagonal
        const bool diag = (k0 == q0);

        __syncthreads();                  // Qs visible / prior Phase B done
        // stage Kt transposed [e][k] (2 threads per key row)
        {
            const int kr = tid >> 1, half = tid & 1;
            const float* kp = &g_k[((size_t)b*SS + k0 + kr)*HH + half*32];
            #pragma unroll
            for (int i = 0; i < 8; i++) {
                float4 t = *(const float4*)&kp[i*4];
                int e = half*32 + i*4;
                KP[(e+0)*AST + kr] = tf32r(t.x);
                KP[(e+1)*AST + kr] = tf32r(t.y);
                KP[(e+2)*AST + kr] = tf32r(t.z);
                KP[(e+3)*AST + kr] = tf32r(t.w);
            }
        }
        // stage V [k][h]
        #pragma unroll
        for (int i = 0; i < 8; i++) {
            int f4 = i*128 + tid;
            int r = f4 >> 4, c4 = f4 & 15;
            float4 t = *(const float4*)&g_v[((size_t)b*SS + k0 + r)*HH + c4*4];
            float* p = &Vs[r*AST + c4*4];
            p[0]=tf32r(t.x); p[1]=tf32r(t.y); p[2]=tf32r(t.z); p[3]=tf32r(t.w);
        }
        __syncthreads();

        // ---- Phase A: S = Qhat Khat^T ----
        float S[8][4] = {};
        #pragma unroll
        for (int ks = 0; ks < 8; ks++) {
            const int kc = ks * 8;
            uint32_t a[4];
            a[0] = __float_as_uint(Qs[(wq+g  )*AST + kc + tig    ]);
            a[1] = __float_as_uint(Qs[(wq+g+8)*AST + kc + tig    ]);
            a[2] = __float_as_uint(Qs[(wq+g  )*AST + kc + tig + 4]);
            a[3] = __float_as_uint(Qs[(wq+g+8)*AST + kc + tig + 4]);
            #pragma unroll
            for (int nt = 0; nt < 8; nt++) {
                uint32_t bf[2];
                bf[0] = __float_as_uint(KP[(kc+tig  )*AST + nt*8 + g]);
                bf[1] = __float_as_uint(KP[(kc+tig+4)*AST + nt*8 + g]);
                mma_tf32(S[nt], a, bf);
            }
        }

        // ---- causal mask (diagonal subtile only) ----
        const int gq0 = q0 + wq + g;      // row of c0/c1
        const int gq1 = gq0 + 8;          // row of c2/c3
        if (diag) {
            #pragma unroll
            for (int nt = 0; nt < 8; nt++) {
                const int kc = k0 + nt*8 + 2*tig;
                if (kc   > gq0) S[nt][0] = -CUDART_INF_F;
                if (kc+1 > gq0) S[nt][1] = -CUDART_INF_F;
                if (kc   > gq1) S[nt][2] = -CUDART_INF_F;
                if (kc+1 > gq1) S[nt][3] = -CUDART_INF_F;
            }
        }

        // ---- online softmax over rows (quad shfl) ----
        float mx0 = -CUDART_INF_F, mx1 = -CUDART_INF_F;
        #pragma unroll
        for (int nt = 0; nt < 8; nt++) {
            mx0 = fmaxf(mx0, fmaxf(S[nt][0], S[nt][1]));
            mx1 = fmaxf(mx1, fmaxf(S[nt][2], S[nt][3]));
        }
        mx0 = fmaxf(mx0, __shfl_xor_sync(0xffffffffu, mx0, 1));
        mx0 = fmaxf(mx0, __shfl_xor_sync(0xffffffffu, mx0, 2));
        mx1 = fmaxf(mx1, __shfl_xor_sync(0xffffffffu, mx1, 1));
        mx1 = fmaxf(mx1, __shfl_xor_sync(0xffffffffu, mx1, 2));

        const float nm0 = fmaxf(m0, mx0), nm1 = fmaxf(m1, mx1);
        const float al0 = __expf(m0 - nm0), al1 = __expf(m1 - nm1);
        m0 = nm0; m1 = nm1;

        float s0 = 0.0f, s1 = 0.0f;
        #pragma unroll
        for (int nt = 0; nt < 8; nt++) {
            S[nt][0] = __expf(S[nt][0] - nm0);
            S[nt][1] = __expf(S[nt][1] - nm0);
            S[nt][2] = __expf(S[nt][2] - nm1);
            S[nt][3] = __expf(S[nt][3] - nm1);
            s0 += S[nt][0] + S[nt][1];
            s1 += S[nt][2] + S[nt][3];
        }
        s0 += __shfl_xor_sync(0xffffffffu, s0, 1);
        s0 += __shfl_xor_sync(0xffffffffu, s0, 2);
        s1 += __shfl_xor_sync(0xffffffffu, s1, 1);
        s1 += __shfl_xor_sync(0xffffffffu, s1, 2);
        l0 = l0*al0 + s0;
        l1 = l1*al1 + s1;
        #pragma unroll
        for (int nt = 0; nt < 8; nt++) {
            O[nt][0] *= al0; O[nt][1] *= al0;
            O[nt][2] *= al1; O[nt][3] *= al1;
        }

        __syncthreads();                  // everyone done reading Kt
        // stage P (tf32) over the Kt region
        #pragma unroll
        for (int nt = 0; nt < 8; nt++) {
            *(float2*)&KP[(wq+g  )*AST + nt*8 + 2*tig] =
                make_float2(tf32r(S[nt][0]), tf32r(S[nt][1]));
            *(float2*)&KP[(wq+g+8)*AST + nt*8 + 2*tig] =
                make_float2(tf32r(S[nt][2]), tf32r(S[nt][3]));
        }
        __syncthreads();

        // ---- Phase B: O += P V ----
        #pragma unroll
        for (int ks = 0; ks < 8; ks++) {
            const int kc = ks * 8;
            uint32_t a[4];
            a[0] = __float_as_uint(KP[(wq+g  )*AST + kc + tig    ]);
            a[1] = __float_as_uint(KP[(wq+g+8)*AST + kc + tig    ]);
            a[2] = __float_as_uint(KP[(wq+g  )*AST + kc + tig + 4]);
            a[3] = __float_as_uint(KP[(wq+g+8)*AST + kc + tig + 4]);
            #pragma unroll
            for (int nt = 0; nt < 8; nt++) {
                uint32_t bf[2];
                bf[0] = __float_as_uint(Vs[(kc+tig  )*AST + nt*8 + g]);
                bf[1] = __float_as_uint(Vs[(kc+tig+4)*AST + nt*8 + g]);
                mma_tf32(O[nt], a, bf);
            }
        }
    }

    // ---- write unnormalized partials + (m, l) ----
    const size_t r0 = (size_t)b*SS + q0 + wq + g;
    const size_t r1 = r0 + 8;
    #pragma unroll
    for (int nt = 0; nt < 8; nt++) {
        const int col = nt*8 + 2*tig;
        *(float2*)&g_opart[(r0*NCH + c)*HH + col] = make_float2(O[nt][0], O[nt][1]);
        *(float2*)&g_opart[(r1*NCH + c)*HH + col] = make_float2(O[nt][2], O[nt][3]);
    }
    if (tig == 0) {
        g_ml[(r0*NCH + c)*2 + 0] = m0;
        g_ml[(r0*NCH + c)*2 + 1] = l0;
        g_ml[(r1*NCH + c)*2 + 0] = m1;
        g_ml[(r1*NCH + c)*2 + 1] = l1;
    }
}

// ==========================================================================
// Kernel 3: combine split-K partials. One block per query row, thread = h.
// ==========================================================================
__global__ __launch_bounds__(64) void attn_combine(float* __restrict__ out)
{
    const size_t r = blockIdx.x;          // 0..8191
    const int    i = (int)(r & (SS - 1)); // position within batch
    const int    e = threadIdx.x;
    const int  nch = i / CH + 1;          // valid chunks for this row

    float M = -CUDART_INF_F;
    #pragma unroll 1
    for (int c = 0; c < nch; c++)
        M = fmaxf(M, g_ml[(r * NCH + c) * 2 + 0]);

    float L = 0.0f, o = 0.0f;
    #pragma unroll 1
    for (int c = 0; c < nch; c++) {
        float mc = g_ml[(r * NCH + c) * 2 + 0];
        float lc = g_ml[(r * NCH + c) * 2 + 1];
        float w  = __expf(mc - M);
        L += lc * w;
        o  = fmaf(w, g_opart[(r * NCH + c) * HH + e], o);
    }
    out[r * HH + e] = o / L;
}

// ==========================================================================
extern "C" void kernel_launch(void* const* d_in, const int* in_sizes, int n_in,
                              void* d_out, int out_size)
{
    const float* x  = (const float*)d_in[0];
    const float* Wq = (const float*)d_in[1];
    const float* bq = (const float*)d_in[2];
    const float* Wk = (const float*)d_in[3];
    const float* bk = (const float*)d_in[4];
    const float* Wv = (const float*)d_in[5];
    const float* bv = (const float*)d_in[6];
    float* out = (float*)d_out;

    cudaFuncSetAttribute(attn_partial,
                         cudaFuncAttributeMaxDynamicSharedMemorySize, ATTN_SMEM);

    dim3 gq(NROWS / 128, 3);
    qkv_proj<<<gq, 256>>>(x, Wq, bq, Wk, bk, Wv, bv);

    dim3 ga(SS / 64, NCH, BB);            // active iff 4c <= qt
    attn_partial<<<ga, 128, ATTN_SMEM>>>();

    attn_combine<<<NROWS, 64>>>(out);
}

// round 8
// speedup vs baseline: 2.7146x; 1.0179x over previous
#include <cuda_runtime.h>
#include <math_constants.h>
#include <cstdint>
#include <cstddef>

// Problem shape (fixed by reference)
#define BB  4
#define SS  2048
#define EE  1024
#define HH  64
#define NROWS (BB*SS)     // 8192 query rows
#define CH  256           // keys per split-K chunk (four 64-key subtiles)
#define NCH (SS/CH)       // 8 chunks per batch

// -------- device scratch (no allocations allowed) --------
__device__ float g_q[NROWS*HH];
__device__ float g_k[NROWS*HH];
__device__ float g_v[NROWS*HH];
__device__ float g_opart[(size_t)NROWS*NCH*HH];
__device__ float g_ml[(size_t)NROWS*NCH*2];

// -------- tf32 helpers --------
__device__ __forceinline__ float tf32r(float x) {
    uint32_t u;
    asm("cvt.rna.tf32.f32 %0, %1;" : "=r"(u) : "f"(x));
    return __uint_as_float(u);
}
__device__ __forceinline__ void mma_tf32(float* d, const uint32_t* a, const uint32_t* b) {
    asm volatile(
        "mma.sync.aligned.m16n8k8.row.col.f32.tf32.tf32.f32 "
        "{%0,%1,%2,%3}, {%4,%5,%6,%7}, {%8,%9}, {%0,%1,%2,%3};"
        : "+f"(d[0]), "+f"(d[1]), "+f"(d[2]), "+f"(d[3])
        : "r"(a[0]), "r"(a[1]), "r"(a[2]), "r"(a[3]), "r"(b[0]), "r"(b[1]));
}
// k-permutation within a 32-wide block: frag cols for all ks become contiguous
__device__ __forceinline__ int perm64(int c) {       // c in 0..63
    return (c & 32) + ((c & 3) << 3) + ((c >> 2) & 7);
}

// ==========================================================================
// Kernel 1: QKV projection, tf32 mma, permuted smem (all frag loads LDS.128).
// Block 128 thr (4 warps); tile M=64 (warp m16), N=64, BK=32.
// xs[row][perm32(k)] stride 36; ws[k][permN(n)] stride 72.
// Grid (8192/64, 3) = 384 blocks.
// ==========================================================================
#define QK_XST 36
#define QK_WST 72

__global__ __launch_bounds__(128) void qkv_proj(
    const float* __restrict__ x,
    const float* __restrict__ Wq, const float* __restrict__ bq,
    const float* __restrict__ Wk, const float* __restrict__ bk,
    const float* __restrict__ Wv, const float* __restrict__ bv)
{
    __shared__ float xs[64*QK_XST];       // 9.2 KB
    __shared__ float ws[32*QK_WST];       // 9.2 KB

    const int tid  = threadIdx.x;
    const int warp = tid >> 5;
    const int lane = tid & 31;
    const int g    = lane >> 2;
    const int tig  = lane & 3;
    const int row0 = blockIdx.x * 64;
    const int mat  = blockIdx.y;

    const float* W    = (mat == 0) ? Wq : (mat == 1) ? Wk : Wv;
    const float* bias = (mat == 0) ? bq : (mat == 1) ? bk : bv;
    float* out        = (mat == 0) ? g_q : (mat == 1) ? g_k : g_v;

    float4 xt[4], wt[4];
    // x tile 64x32 = 512 float4; W tile 32x64 = 512 float4; 4 each per thread
    #pragma unroll
    for (int i = 0; i < 4; i++) {
        int f4 = i*128 + tid;
        xt[i] = *(const float4*)&x[(size_t)(row0 + (f4>>3))*EE + (f4&7)*4];
        wt[i] = *(const float4*)&W[(size_t)(f4>>4)*HH + (f4&15)*4];
    }

    float acc[8][4] = {};

    #pragma unroll 1
    for (int kb = 0; kb < EE; kb += 32) {
        // ---- stage (tf32-rounded, permuted) ----
        #pragma unroll
        for (int i = 0; i < 4; i++) {
            int f4 = i*128 + tid;
            int r = f4 >> 3, c4 = f4 & 7;        // x: perm32(c)=j*8+c4
            float* p = &xs[r*QK_XST + c4];
            p[0]  = tf32r(xt[i].x); p[8]  = tf32r(xt[i].y);
            p[16] = tf32r(xt[i].z); p[24] = tf32r(xt[i].w);
            int rw = f4 >> 4, c4w = f4 & 15;     // W: permN(n)=(n&7)*8+(n>>3)
            int n0 = c4w*4;
            float* q0 = &ws[rw*QK_WST];
            q0[((n0+0)&7)*8 + ((n0+0)>>3)] = tf32r(wt[i].x);
            q0[((n0+1)&7)*8 + ((n0+1)>>3)] = tf32r(wt[i].y);
            q0[((n0+2)&7)*8 + ((n0+2)>>3)] = tf32r(wt[i].z);
            q0[((n0+3)&7)*8 + ((n0+3)>>3)] = tf32r(wt[i].w);
        }
        __syncthreads();

        if (kb + 32 < EE) {
            #pragma unroll
            for (int i = 0; i < 4; i++) {
                int f4 = i*128 + tid;
                xt[i] = *(const float4*)&x[(size_t)(row0 + (f4>>3))*EE + kb+32 + (f4&7)*4];
                wt[i] = *(const float4*)&W[(size_t)(kb+32 + (f4>>4))*HH + (f4&15)*4];
            }
        }

        // ---- fragment compute: all LDS.128 ----
        const int rb = warp*16 + g;
        float al[8], ah[8];
        *(float4*)&al[0] = *(const float4*)&xs[ rb   *QK_XST + tig*8    ];
        *(float4*)&al[4] = *(const float4*)&xs[ rb   *QK_XST + tig*8 + 4];
        *(float4*)&ah[0] = *(const float4*)&xs[(rb+8)*QK_XST + tig*8    ];
        *(float4*)&ah[4] = *(const float4*)&xs[(rb+8)*QK_XST + tig*8 + 4];

        #pragma unroll
        for (int ks = 0; ks < 4; ks++) {
            float w1[8], w2[8];
            *(float4*)&w1[0] = *(const float4*)&ws[(8*ks+tig  )*QK_WST + g*8    ];
            *(float4*)&w1[4] = *(const float4*)&ws[(8*ks+tig  )*QK_WST + g*8 + 4];
            *(float4*)&w2[0] = *(const float4*)&ws[(8*ks+tig+4)*QK_WST + g*8    ];
            *(float4*)&w2[4] = *(const float4*)&ws[(8*ks+tig+4)*QK_WST + g*8 + 4];
            uint32_t a[4];
            a[0] = __float_as_uint(al[2*ks  ]);
            a[1] = __float_as_uint(ah[2*ks  ]);
            a[2] = __float_as_uint(al[2*ks+1]);
            a[3] = __float_as_uint(ah[2*ks+1]);
            #pragma unroll
            for (int nt = 0; nt < 8; nt++) {
                uint32_t bf[2] = { __float_as_uint(w1[nt]), __float_as_uint(w2[nt]) };
                mma_tf32(acc[nt], a, bf);
            }
        }
        __syncthreads();
    }

    #pragma unroll
    for (int nt = 0; nt < 8; nt++) {
        const int row = row0 + warp*16 + g;
        const int col = nt*8 + 2*tig;
        const float b0 = __ldg(&bias[col]);
        const float b1 = __ldg(&bias[col+1]);
        *(float2*)&out[(size_t) row   *HH + col] =
            make_float2(acc[nt][0] + b0, acc[nt][1] + b1);
        *(float2*)&out[(size_t)(row+8)*HH + col] =
            make_float2(acc[nt][2] + b0, acc[nt][3] + b1);
    }
}

// ==========================================================================
// Kernel 2: split-K causal flash attention; permuted smem fragment layouts.
// Block 128 thr (4 warps); 64 q-rows x 256 keys (four 64-key subtiles).
// Qs[q][perm64(e)], Ks[key][perm64(e)] (overlaid by Ps[q][perm64(key)]),
// Vst[h][perm64(key)], all stride 72.
// Grid (qt=32, c=8, b=4); active iff 4c <= qt.
// ==========================================================================
#define AST 72
#define ATTN_SMEM (3*64*AST*4)   // 55.3 KB

__global__ __launch_bounds__(128) void attn_partial()
{
    extern __shared__ float dsm[];
    float* Qs  = dsm;
    float* KPs = dsm + 64*AST;            // Ks, overlaid by Ps
    float* Vst = dsm + 2*64*AST;

    const int tid  = threadIdx.x;
    const int warp = tid >> 5;
    const int lane = tid & 31;
    const int g    = lane >> 2;
    const int tig  = lane & 3;
    const int qt   = blockIdx.x;
    const int c    = blockIdx.y;
    const int b    = blockIdx.z;
    if (4*c > qt) return;

    const int q0 = qt * 64;
    const int wq = warp * 16;

    // ---- stage Q (scaled, tf32, e-permuted) ----
    #pragma unroll
    for (int i = 0; i < 8; i++) {
        int f4 = i*128 + tid;
        int r = f4 >> 4, c4 = f4 & 15;
        float4 t = *(const float4*)&g_q[((size_t)b*SS + q0 + r)*HH + c4*4];
        float* p = &Qs[r*AST + ((c4&8)<<2) + (c4&7)];
        p[0]  = tf32r(t.x*0.125f); p[8]  = tf32r(t.y*0.125f);
        p[16] = tf32r(t.z*0.125f); p[24] = tf32r(t.w*0.125f);
    }

    float O[8][4] = {};
    float m0 = -CUDART_INF_F, m1 = -CUDART_INF_F;
    float l0 = 0.0f, l1 = 0.0f;

    #pragma unroll 1
    for (int sub = 0; sub < 4; sub++) {
        const int k0 = c*CH + sub*64;
        if (k0 > q0) break;
        const bool diag = (k0 == q0);

        __syncthreads();                  // prior phase done; Qs visible
        // ---- stage K rows (e-permuted) ----
        #pragma unroll
        for (int i = 0; i < 8; i++) {
            int f4 = i*128 + tid;
            int r = f4 >> 4, c4 = f4 & 15;
            float4 t = *(const float4*)&g_k[((size_t)b*SS + k0 + r)*HH + c4*4];
            float* p = &KPs[r*AST + ((c4&8)<<2) + (c4&7)];
            p[0]  = tf32r(t.x); p[8]  = tf32r(t.y);
            p[16] = tf32r(t.z); p[24] = tf32r(t.w);
        }
        // ---- stage V transposed: Vst[h][perm64(key)] (thread pairs) ----
        {
            const int kr = tid >> 1, half = tid & 1;
            const int pk = perm64(kr);
            const float* vp = &g_v[((size_t)b*SS + k0 + kr)*HH + half*32];
            #pragma unroll
            for (int i = 0; i < 8; i++) {
                float4 t = *(const float4*)&vp[i*4];
                int h = half*32 + i*4;
                Vst[(h+0)*AST + pk] = tf32r(t.x);
                Vst[(h+1)*AST + pk] = tf32r(t.y);
                Vst[(h+2)*AST + pk] = tf32r(t.z);
                Vst[(h+3)*AST + pk] = tf32r(t.w);
            }
        }
        __syncthreads();

        // ---- Phase A: S = Qhat Khat^T ----
        float S[8][4] = {};
        #pragma unroll
        for (int eb = 0; eb < 2; eb++) {
            float al[8], ah[8];
            *(float4*)&al[0] = *(const float4*)&Qs[(wq+g  )*AST + eb*32 + tig*8    ];
            *(float4*)&al[4] = *(const float4*)&Qs[(wq+g  )*AST + eb*32 + tig*8 + 4];
            *(float4*)&ah[0] = *(const float4*)&Qs[(wq+g+8)*AST + eb*32 + tig*8    ];
            *(float4*)&ah[4] = *(const float4*)&Qs[(wq+g+8)*AST + eb*32 + tig*8 + 4];
            #pragma unroll
            for (int nh = 0; nh < 2; nh++) {      // 4 nt at a time
                float kv[4][8];
                #pragma unroll
                for (int j = 0; j < 4; j++) {
                    int nt = nh*4 + j;
                    *(float4*)&kv[j][0] = *(const float4*)&KPs[(nt*8+g)*AST + eb*32 + tig*8    ];
                    *(float4*)&kv[j][4] = *(const float4*)&KPs[(nt*8+g)*AST + eb*32 + tig*8 + 4];
                }
                #pragma unroll
                for (int k2 = 0; k2 < 4; k2++) {
                    uint32_t a[4];
                    a[0] = __float_as_uint(al[2*k2  ]);
                    a[1] = __float_as_uint(ah[2*k2  ]);
                    a[2] = __float_as_uint(al[2*k2+1]);
                    a[3] = __float_as_uint(ah[2*k2+1]);
                    #pragma unroll
                    for (int j = 0; j < 4; j++) {
                        uint32_t bf[2] = { __float_as_uint(kv[j][2*k2]),
                                           __float_as_uint(kv[j][2*k2+1]) };
                        mma_tf32(S[nh*4+j], a, bf);
                    }
                }
            }
        }

        // ---- causal mask (diagonal subtile only) ----
        const int gq0 = q0 + wq + g;
        const int gq1 = gq0 + 8;
        if (diag) {
            #pragma unroll
            for (int nt = 0; nt < 8; nt++) {
                const int kc = k0 + nt*8 + 2*tig;
                if (kc   > gq0) S[nt][0] = -CUDART_INF_F;
                if (kc+1 > gq0) S[nt][1] = -CUDART_INF_F;
                if (kc   > gq1) S[nt][2] = -CUDART_INF_F;
                if (kc+1 > gq1) S[nt][3] = -CUDART_INF_F;
            }
        }

        // ---- online softmax (quad shfl) ----
        float mx0 = -CUDART_INF_F, mx1 = -CUDART_INF_F;
        #pragma unroll
        for (int nt = 0; nt < 8; nt++) {
            mx0 = fmaxf(mx0, fmaxf(S[nt][0], S[nt][1]));
            mx1 = fmaxf(mx1, fmaxf(S[nt][2], S[nt][3]));
        }
        mx0 = fmaxf(mx0, __shfl_xor_sync(0xffffffffu, mx0, 1));
        mx0 = fmaxf(mx0, __shfl_xor_sync(0xffffffffu, mx0, 2));
        mx1 = fmaxf(mx1, __shfl_xor_sync(0xffffffffu, mx1, 1));
        mx1 = fmaxf(mx1, __shfl_xor_sync(0xffffffffu, mx1, 2));

        const float nm0 = fmaxf(m0, mx0), nm1 = fmaxf(m1, mx1);
        const float al0 = __expf(m0 - nm0), al1 = __expf(m1 - nm1);
        m0 = nm0; m1 = nm1;

        float s0 = 0.0f, s1 = 0.0f;
        #pragma unroll
        for (int nt = 0; nt < 8; nt++) {
            S[nt][0] = __expf(S[nt][0] - nm0);
            S[nt][1] = __expf(S[nt][1] - nm0);
            S[nt][2] = __expf(S[nt][2] - nm1);
            S[nt][3] = __expf(S[nt][3] - nm1);
            s0 += S[nt][0] + S[nt][1];
            s1 += S[nt][2] + S[nt][3];
        }
        s0 += __shfl_xor_sync(0xffffffffu, s0, 1);
        s0 += __shfl_xor_sync(0xffffffffu, s0, 2);
        s1 += __shfl_xor_sync(0xffffffffu, s1, 1);
        s1 += __shfl_xor_sync(0xffffffffu, s1, 2);
        l0 = l0*al0 + s0;
        l1 = l1*al1 + s1;
        #pragma unroll
        for (int nt = 0; nt < 8; nt++) {
            O[nt][0] *= al0; O[nt][1] *= al0;
            O[nt][2] *= al1; O[nt][3] *= al1;
        }

        __syncthreads();                  // Ks reads complete
        // ---- stage P over Ks region: Ps[q][perm64(key)] ----
        #pragma unroll
        for (int nt = 0; nt < 8; nt++) {
            const int p0 = perm64(nt*8 + 2*tig);      // key0+1 -> p0+8
            KPs[(wq+g  )*AST + p0    ] = tf32r(S[nt][0]);
            KPs[(wq+g  )*AST + p0 + 8] = tf32r(S[nt][1]);
            KPs[(wq+g+8)*AST + p0    ] = tf32r(S[nt][2]);
            KPs[(wq+g+8)*AST + p0 + 8] = tf32r(S[nt][3]);
        }
        __syncthreads();

        // ---- Phase B: O += P V ----
        #pragma unroll
        for (int kb = 0; kb < 2; kb++) {
            float al[8], ah[8];
            *(float4*)&al[0] = *(const float4*)&KPs[(wq+g  )*AST + kb*32 + tig*8    ];
            *(float4*)&al[4] = *(const float4*)&KPs[(wq+g  )*AST + kb*32 + tig*8 + 4];
            *(float4*)&ah[0] = *(const float4*)&KPs[(wq+g+8)*AST + kb*32 + tig*8    ];
            *(float4*)&ah[4] = *(const float4*)&KPs[(wq+g+8)*AST + kb*32 + tig*8 + 4];
            #pragma unroll
            for (int nh = 0; nh < 2; nh++) {
                float vv[4][8];
                #pragma unroll
                for (int j = 0; j < 4; j++) {
                    int nt = nh*4 + j;
                    *(float4*)&vv[j][0] = *(const float4*)&Vst[(nt*8+g)*AST + kb*32 + tig*8    ];
                    *(float4*)&vv[j][4] = *(const float4*)&Vst[(nt*8+g)*AST + kb*32 + tig*8 + 4];
                }
                #pragma unroll
                for (int k2 = 0; k2 < 4; k2++) {
                    uint32_t a[4];
                    a[0] = __float_as_uint(al[2*k2  ]);
                    a[1] = __float_as_uint(ah[2*k2  ]);
                    a[2] = __float_as_uint(al[2*k2+1]);
                    a[3] = __float_as_uint(ah[2*k2+1]);
                    #pragma unroll
                    for (int j = 0; j < 4; j++) {
                        uint32_t bf[2] = { __float_as_uint(vv[j][2*k2]),
                                           __float_as_uint(vv[j][2*k2+1]) };
                        mma_tf32(O[nh*4+j], a, bf);
                    }
                }
            }
        }
    }

    // ---- write unnormalized partials + (m, l) ----
    const size_t r0 = (size_t)b*SS + q0 + wq + g;
    const size_t r1 = r0 + 8;
    #pragma unroll
    for (int nt = 0; nt < 8; nt++) {
        const int col = nt*8 + 2*tig;
        *(float2*)&g_opart[(r0*NCH + c)*HH + col] = make_float2(O[nt][0], O[nt][1]);
        *(float2*)&g_opart[(r1*NCH + c)*HH + col] = make_float2(O[nt][2], O[nt][3]);
    }
    if (tig == 0) {
        g_ml[(r0*NCH + c)*2 + 0] = m0;
        g_ml[(r0*NCH + c)*2 + 1] = l0;
        g_ml[(r1*NCH + c)*2 + 0] = m1;
        g_ml[(r1*NCH + c)*2 + 1] = l1;
    }
}

// ==========================================================================
// Kernel 3: combine split-K partials. One block per query row, thread = h.
// ==========================================================================
__global__ __launch_bounds__(64) void attn_combine(float* __restrict__ out)
{
    const size_t r = blockIdx.x;
    const int    i = (int)(r & (SS - 1));
    const int    e = threadIdx.x;
    const int  nch = i / CH + 1;

    float M = -CUDART_INF_F;
    #pragma unroll 1
    for (int c = 0; c < nch; c++)
        M = fmaxf(M, g_ml[(r * NCH + c) * 2 + 0]);

    float L = 0.0f, o = 0.0f;
    #pragma unroll 1
    for (int c = 0; c < nch; c++) {
        float mc = g_ml[(r * NCH + c) * 2 + 0];
        float lc = g_ml[(r * NCH + c) * 2 + 1];
        float w  = __expf(mc - M);
        L += lc * w;
        o  = fmaf(w, g_opart[(r * NCH + c) * HH + e], o);
    }
    out[r * HH + e] = o / L;
}

// ==========================================================================
extern "C" void kernel_launch(void* const* d_in, const int* in_sizes, int n_in,
                              void* d_out, int out_size)
{
    const float* x  = (const float*)d_in[0];
    const float* Wq = (const float*)d_in[1];
    const float* bq = (const float*)d_in[2];
    const float* Wk = (const float*)d_in[3];
    const float* bk = (const float*)d_in[4];
    const float* Wv = (const float*)d_in[5];
    const float* bv = (const float*)d_in[6];
    float* out = (float*)d_out;

    cudaFuncSetAttribute(attn_partial,
                         cudaFuncAttributeMaxDynamicSharedMemorySize, ATTN_SMEM);

    dim3 gq(NROWS / 64, 3);
    qkv_proj<<<gq, 128>>>(x, Wq, bq, Wk, bk, Wv, bv);

    dim3 ga(SS / 64, NCH, BB);
    attn_partial<<<ga, 128, ATTN_SMEM>>>();

    attn_combine<<<NROWS, 64>>>(out);
}